// round 1
// baseline (speedup 1.0000x reference)
#include <cuda_runtime.h>
#include <math.h>
#include <stdint.h>

// Problem constants (fixed shapes per reference)
#define NP_MAX 50000
#define NHE_MAX 5000
#define DIN 128

// Device scratch (no allocations allowed)
__device__ float g_he_feat[NHE_MAX * DIN];      // 2.56 MB
__device__ float g_he_weighted[NHE_MAX * DIN];  // 2.56 MB
__device__ float g_cluster[NP_MAX * DIN];       // 25.6 MB

// ---------------------------------------------------------------------------
// Zero scratch buffers (he_feat + cluster receive atomics and must start at 0)
// ---------------------------------------------------------------------------
__global__ void zero_bufs_kernel() {
    int i = blockIdx.x * blockDim.x + threadIdx.x;
    float4 z = {0.f, 0.f, 0.f, 0.f};
    if (i < (NHE_MAX * DIN) / 4) ((float4*)g_he_feat)[i] = z;
    if (i < (NP_MAX * DIN) / 4)  ((float4*)g_cluster)[i] = z;
}

// ---------------------------------------------------------------------------
// Stage 1: he_feat[hid] += feat[pid] * ew   (warp per edge, red.v4 atomics)
// ---------------------------------------------------------------------------
__global__ void scatter_he_kernel(const float* __restrict__ feat,
                                  const float* __restrict__ ew,
                                  const int* __restrict__ pid,
                                  const int* __restrict__ hid, int nE) {
    int gt = blockIdx.x * blockDim.x + threadIdx.x;
    int e = gt >> 5;
    int lane = gt & 31;
    if (e >= nE) return;
    int p = __ldg(pid + e);
    int h = __ldg(hid + e);
    float w = __ldg(ew + e);
    float4 v = __ldg(((const float4*)feat) + p * 32 + lane);
    float* dst = g_he_feat + h * 128 + lane * 4;
    asm volatile("red.global.add.v4.f32 [%0], {%1,%2,%3,%4};"
                 :: "l"(dst), "f"(v.x * w), "f"(v.y * w), "f"(v.z * w), "f"(v.w * w)
                 : "memory");
}

// ---------------------------------------------------------------------------
// Stage 2: per-hyperedge attention -> he_weighted
// 8 hyperedges per block (reuses Wh1 across them), 256 threads = 4 heads x 64
// ---------------------------------------------------------------------------
__global__ void he_attn_kernel(const float* __restrict__ Wh1,
                               const float* __restrict__ bh1,
                               const float* __restrict__ Wh2,
                               const float* __restrict__ bh2,
                               const float* __restrict__ Wfuse, int nHE) {
    __shared__ float f[8][128];
    __shared__ float sred[8][4];
    __shared__ float satt[8];
    int tid = threadIdx.x;
    int n0 = blockIdx.x * 8;

    for (int idx = tid; idx < 1024; idx += 256) {
        int e = idx >> 7, d = idx & 127;
        int ne = n0 + e;
        f[e][d] = (ne < nHE) ? g_he_feat[ne * 128 + d] : 0.f;
    }
    if (tid < 32) ((float*)sred)[tid] = 0.f;
    __syncthreads();

    int h = tid >> 6, k = tid & 63;
    float acc[8];
#pragma unroll
    for (int e = 0; e < 8; e++) acc[e] = 0.f;

    const float* wp = Wh1 + h * 128 * 64 + k;
#pragma unroll 4
    for (int d = 0; d < 128; d++) {
        float w = __ldg(wp + d * 64);
#pragma unroll
        for (int e = 0; e < 8; e++) acc[e] += f[e][d] * w;
    }
    float b1 = __ldg(bh1 + h * 64 + k);
    float w2 = __ldg(Wh2 + h * 64 + k);
#pragma unroll
    for (int e = 0; e < 8; e++) {
        float v = fmaxf(acc[e] + b1, 0.f) * w2;
#pragma unroll
        for (int o = 16; o; o >>= 1) v += __shfl_xor_sync(0xffffffffu, v, o);
        if ((tid & 31) == 0) atomicAdd(&sred[e][h], v);
    }
    __syncthreads();

    if (tid < 8) {
        float a = 0.f;
#pragma unroll
        for (int hh = 0; hh < 4; hh++) {
            float s = 1.f / (1.f + expf(-(sred[tid][hh] + bh2[hh])));
            a += s * Wfuse[hh];
        }
        satt[tid] = a;
    }
    __syncthreads();

    for (int idx = tid; idx < 1024; idx += 256) {
        int e = idx >> 7, d = idx & 127;
        int ne = n0 + e;
        if (ne < nHE) g_he_weighted[ne * 128 + d] = f[e][d] * satt[e];
    }
}

// ---------------------------------------------------------------------------
// Stage 3: cluster[pid] += he_weighted[hid] * ew
// ---------------------------------------------------------------------------
__global__ void scatter_cluster_kernel(const float* __restrict__ ew,
                                       const int* __restrict__ pid,
                                       const int* __restrict__ hid, int nE) {
    int gt = blockIdx.x * blockDim.x + threadIdx.x;
    int e = gt >> 5;
    int lane = gt & 31;
    if (e >= nE) return;
    int p = __ldg(pid + e);
    int h = __ldg(hid + e);
    float w = __ldg(ew + e);
    float4 v = *(const float4*)(g_he_weighted + h * 128 + lane * 4);
    float* dst = g_cluster + p * 128 + lane * 4;
    asm volatile("red.global.add.v4.f32 [%0], {%1,%2,%3,%4};"
                 :: "l"(dst), "f"(v.x * w), "f"(v.y * w), "f"(v.z * w), "f"(v.w * w)
                 : "memory");
}

// ---------------------------------------------------------------------------
// Stage 4: fused per-protein MLP. 64 rows per block, 256 threads.
// Uses fma.rn.f32x2 (FFMA2) packed fp32 for 2x fp32 throughput.
// ---------------------------------------------------------------------------
#define TM 64
#define LDA_F 132   // padded stride for 128-wide tiles (conflict-free)
#define LDA_C 260   // padded stride for 256-wide tiles

// smem float offsets
#define OFF_R1  0               // 16896 floats: sFeat(64x132)+sClu(64x132); later sT1(64x260)
#define OFF_CAT 16896           // 16640 floats: cat = [self_f | clu_f]
#define OFF_W   33536           // 8192 floats: weight tile 64x128
#define OFF_T2  41728           // 8448 floats: t2 64x132
#define OFF_FW  50176           // 128 floats: per-row softmax weights
#define SMEM_FLOATS 50304

__device__ __forceinline__ unsigned long long pack2(float x) {
    unsigned long long r;
    unsigned int xi = __float_as_uint(x);
    asm("mov.b64 %0, {%1, %1};" : "=l"(r) : "r"(xi));
    return r;
}
__device__ __forceinline__ void fma2(unsigned long long& d, unsigned long long a,
                                     unsigned long long b) {
    asm("fma.rn.f32x2 %0, %1, %2, %0;" : "+l"(d) : "l"(a), "l"(b));
}
__device__ __forceinline__ float2 unpack2(unsigned long long v) {
    unsigned int lo, hi;
    asm("mov.b64 {%0, %1}, %2;" : "=r"(lo), "=r"(hi) : "l"(v));
    float2 f;
    f.x = __uint_as_float(lo);
    f.y = __uint_as_float(hi);
    return f;
}

// OUT[64 x 128] = act(A[64 x K] @ W[K x NW][:, colOff:colOff+128] + bias)
template <int K, bool RELU>
__device__ __forceinline__ void gemm_tile(const float* __restrict__ W, int NW, int colOff,
                                          const float* __restrict__ bias,
                                          const float* sA, int lda,
                                          float* sOut, int ldo, int outOff,
                                          float* sW, int tid) {
    int tx = tid & 15;        // column group: cols tx*8 .. tx*8+7
    int ty = tid >> 4;        // row group: rows ty*4 .. ty*4+3
    unsigned long long acc[4][4];
#pragma unroll
    for (int r = 0; r < 4; r++)
#pragma unroll
        for (int j = 0; j < 4; j++) acc[r][j] = 0ull;

    for (int k0 = 0; k0 < K; k0 += 64) {
        // stage 64x128 weight tile
        for (int idx = tid; idx < 64 * 32; idx += 256) {
            int r = idx >> 5, c = (idx & 31) << 2;
            *(float4*)(sW + r * 128 + c) =
                *(const float4*)(W + (size_t)(k0 + r) * NW + colOff + c);
        }
        __syncthreads();
#pragma unroll 4
        for (int k = 0; k < 64; k++) {
            const float* ap = sA + k0 + k;
            unsigned long long a0 = pack2(ap[(ty * 4 + 0) * lda]);
            unsigned long long a1 = pack2(ap[(ty * 4 + 1) * lda]);
            unsigned long long a2 = pack2(ap[(ty * 4 + 2) * lda]);
            unsigned long long a3 = pack2(ap[(ty * 4 + 3) * lda]);
            const unsigned long long* bp =
                (const unsigned long long*)(sW + k * 128 + tx * 8);
            unsigned long long b0 = bp[0], b1 = bp[1], b2 = bp[2], b3 = bp[3];
            fma2(acc[0][0], a0, b0); fma2(acc[0][1], a0, b1);
            fma2(acc[0][2], a0, b2); fma2(acc[0][3], a0, b3);
            fma2(acc[1][0], a1, b0); fma2(acc[1][1], a1, b1);
            fma2(acc[1][2], a1, b2); fma2(acc[1][3], a1, b3);
            fma2(acc[2][0], a2, b0); fma2(acc[2][1], a2, b1);
            fma2(acc[2][2], a2, b2); fma2(acc[2][3], a2, b3);
            fma2(acc[3][0], a3, b0); fma2(acc[3][1], a3, b1);
            fma2(acc[3][2], a3, b2); fma2(acc[3][3], a3, b3);
        }
        __syncthreads();
    }
    // epilogue: bias + activation -> smem
#pragma unroll
    for (int j = 0; j < 4; j++) {
        int col = tx * 8 + j * 2;
        float bv0 = __ldg(bias + colOff + col);
        float bv1 = __ldg(bias + colOff + col + 1);
#pragma unroll
        for (int r = 0; r < 4; r++) {
            float2 v = unpack2(acc[r][j]);
            v.x += bv0;
            v.y += bv1;
            if (RELU) { v.x = fmaxf(v.x, 0.f); v.y = fmaxf(v.y, 0.f); }
            sOut[(ty * 4 + r) * ldo + outOff + col] = v.x;
            sOut[(ty * 4 + r) * ldo + outOff + col + 1] = v.y;
        }
    }
}

__global__ void __launch_bounds__(256, 1)
fused_mlp_kernel(const float* __restrict__ feat,
                 const float* __restrict__ Wself, const float* __restrict__ bself,
                 const float* __restrict__ Wclu, const float* __restrict__ bclu,
                 const float* __restrict__ Wf1, const float* __restrict__ bf1,
                 const float* __restrict__ Wf2, const float* __restrict__ bf2,
                 const float* __restrict__ Wf3, const float* __restrict__ bf3,
                 float* __restrict__ out, int nP) {
    extern __shared__ float sm[];
    float* sFeat = sm + OFF_R1;
    float* sClu  = sm + OFF_R1 + TM * LDA_F;
    float* sT1   = sm + OFF_R1;   // overlays sFeat/sClu (dead after projections)
    float* sCat  = sm + OFF_CAT;
    float* sW    = sm + OFF_W;
    float* sT2   = sm + OFF_T2;
    float* sFW   = sm + OFF_FW;

    int tid = threadIdx.x;
    int row0 = blockIdx.x * TM;

    // load feat + cluster tiles
    for (int idx = tid; idx < TM * 32; idx += 256) {
        int r = idx >> 5, c = (idx & 31) << 2;
        int grow = row0 + r;
        float4 f = {0.f, 0.f, 0.f, 0.f};
        float4 cl = f;
        if (grow < nP) {
            f  = *(const float4*)(feat + (size_t)grow * 128 + c);
            cl = *(const float4*)(g_cluster + (size_t)grow * 128 + c);
        }
        *(float4*)(sFeat + r * LDA_F + c) = f;
        *(float4*)(sClu + r * LDA_F + c) = cl;
    }
    // gemm_tile's internal __syncthreads after weight staging orders the tile loads

    // self_f -> cat[:,0:128], clu_f -> cat[:,128:256]
    gemm_tile<128, false>(Wself, 128, 0, bself, sFeat, LDA_F, sCat, LDA_C, 0, sW, tid);
    gemm_tile<128, false>(Wclu, 128, 0, bclu, sClu, LDA_F, sCat, LDA_C, 128, sW, tid);
    // t1 = relu(cat @ Wf1 + bf1)   (two 128-col passes)
    gemm_tile<256, true>(Wf1, 256, 0, bf1, sCat, LDA_C, sT1, LDA_C, 0, sW, tid);
    gemm_tile<256, true>(Wf1, 256, 128, bf1, sCat, LDA_C, sT1, LDA_C, 128, sW, tid);
    // t2 = relu(t1 @ Wf2 + bf2)
    gemm_tile<256, true>(Wf2, 128, 0, bf2, sT1, LDA_C, sT2, LDA_F, 0, sW, tid);
    __syncthreads();

    // logits = t2 @ Wf3 + bf3 ; fw = softmax(logits)
    if (tid < TM) {
        float l0 = bf3[0], l1 = bf3[1];
        const float* t2row = sT2 + tid * LDA_F;
#pragma unroll 8
        for (int k = 0; k < 128; k++) {
            float v = t2row[k];
            l0 += v * __ldg(Wf3 + 2 * k);
            l1 += v * __ldg(Wf3 + 2 * k + 1);
        }
        float w0 = 1.f / (1.f + expf(l1 - l0));
        sFW[tid * 2] = w0;
        sFW[tid * 2 + 1] = 1.f - w0;
    }
    __syncthreads();

    // out = relu(self_f*fw0 + clu_f*fw1 + feat)
    for (int idx = tid; idx < TM * 32; idx += 256) {
        int r = idx >> 5, c = (idx & 31) << 2;
        int grow = row0 + r;
        if (grow >= nP) continue;
        float w0 = sFW[r * 2], w1 = sFW[r * 2 + 1];
        float4 f = *(const float4*)(feat + (size_t)grow * 128 + c);
        const float* catr = sCat + r * LDA_C;
        float4 o;
        o.x = fmaxf(catr[c + 0] * w0 + catr[128 + c + 0] * w1 + f.x, 0.f);
        o.y = fmaxf(catr[c + 1] * w0 + catr[128 + c + 1] * w1 + f.y, 0.f);
        o.z = fmaxf(catr[c + 2] * w0 + catr[128 + c + 2] * w1 + f.z, 0.f);
        o.w = fmaxf(catr[c + 3] * w0 + catr[128 + c + 3] * w1 + f.w, 0.f);
        *(float4*)(out + (size_t)grow * 128 + c) = o;
    }
}

// ---------------------------------------------------------------------------
extern "C" void kernel_launch(void* const* d_in, const int* in_sizes, int n_in,
                              void* d_out, int out_size) {
    const float* feat   = (const float*)d_in[0];
    const float* edge_w = (const float*)d_in[1];
    const float* Wself  = (const float*)d_in[2];
    const float* bself  = (const float*)d_in[3];
    const float* Wclu   = (const float*)d_in[4];
    const float* bclu   = (const float*)d_in[5];
    const float* Wh1    = (const float*)d_in[6];
    const float* bh1    = (const float*)d_in[7];
    const float* Wh2    = (const float*)d_in[8];
    const float* bh2    = (const float*)d_in[9];
    const float* Wfuse  = (const float*)d_in[10];
    const float* Wf1    = (const float*)d_in[11];
    const float* bf1    = (const float*)d_in[12];
    const float* Wf2    = (const float*)d_in[13];
    const float* bf2    = (const float*)d_in[14];
    const float* Wf3    = (const float*)d_in[15];
    const float* bf3    = (const float*)d_in[16];
    const int* edge_pid = (const int*)d_in[17];
    const int* edge_hid = (const int*)d_in[18];

    int nP  = in_sizes[0] / 128;
    int nE  = in_sizes[17];
    int nHE = NHE_MAX;  // fixed problem size (scalar lives on device)

    // zero atomic targets
    zero_bufs_kernel<<<(NP_MAX * DIN / 4 + 255) / 256, 256>>>();

    // he_feat scatter
    {
        long long threads = (long long)nE * 32;
        int blocks = (int)((threads + 255) / 256);
        scatter_he_kernel<<<blocks, 256>>>(feat, edge_w, edge_pid, edge_hid, nE);
    }

    // hyperedge attention
    he_attn_kernel<<<(nHE + 7) / 8, 256>>>(Wh1, bh1, Wh2, bh2, Wfuse, nHE);

    // cluster scatter
    {
        long long threads = (long long)nE * 32;
        int blocks = (int)((threads + 255) / 256);
        scatter_cluster_kernel<<<blocks, 256>>>(edge_w, edge_pid, edge_hid, nE);
    }

    // fused MLP
    cudaFuncSetAttribute(fused_mlp_kernel, cudaFuncAttributeMaxDynamicSharedMemorySize,
                         SMEM_FLOATS * 4);
    fused_mlp_kernel<<<(nP + TM - 1) / TM, 256, SMEM_FLOATS * 4>>>(
        feat, Wself, bself, Wclu, bclu, Wf1, bf1, Wf2, bf2, Wf3, bf3,
        (float*)d_out, nP);
}

// round 2
// speedup vs baseline: 1.2599x; 1.2599x over previous
#include <cuda_runtime.h>
#include <math.h>
#include <stdint.h>

#define NP_MAX 50000
#define NHE_MAX 5000
#define DIN 128

// Device scratch (no allocations allowed)
__device__ float g_he_feat[NHE_MAX * DIN];       // 2.56 MB
__device__ float g_he_weighted[NHE_MAX * DIN];   // 2.56 MB
__device__ float g_cluster[NP_MAX * DIN];        // 25.6 MB
__device__ float g_cat[NP_MAX * 256];            // 51.2 MB  [self_f | clu_f]
__device__ float g_t1[NP_MAX * 256];             // 51.2 MB  relu(cat@Wf1+bf1)

// ---------------------------------------------------------------------------
__global__ void zero_bufs_kernel() {
    int i = blockIdx.x * blockDim.x + threadIdx.x;
    float4 z = {0.f, 0.f, 0.f, 0.f};
    if (i < (NHE_MAX * DIN) / 4) ((float4*)g_he_feat)[i] = z;
    if (i < (NP_MAX * DIN) / 4)  ((float4*)g_cluster)[i] = z;
}

// ---------------------------------------------------------------------------
// Stage 1: he_feat[hid] += feat[pid] * ew   (warp per edge, red.v4 atomics)
// ---------------------------------------------------------------------------
__global__ void scatter_he_kernel(const float* __restrict__ feat,
                                  const float* __restrict__ ew,
                                  const int* __restrict__ pid,
                                  const int* __restrict__ hid, int nE) {
    int gt = blockIdx.x * blockDim.x + threadIdx.x;
    int e = gt >> 5;
    int lane = gt & 31;
    if (e >= nE) return;
    int p = __ldg(pid + e);
    int h = __ldg(hid + e);
    float w = __ldg(ew + e);
    float4 v = __ldg(((const float4*)feat) + p * 32 + lane);
    float* dst = g_he_feat + h * 128 + lane * 4;
    asm volatile("red.global.add.v4.f32 [%0], {%1,%2,%3,%4};"
                 :: "l"(dst), "f"(v.x * w), "f"(v.y * w), "f"(v.z * w), "f"(v.w * w)
                 : "memory");
}

// ---------------------------------------------------------------------------
// Stage 2: per-hyperedge attention -> he_weighted
// ---------------------------------------------------------------------------
__global__ void he_attn_kernel(const float* __restrict__ Wh1,
                               const float* __restrict__ bh1,
                               const float* __restrict__ Wh2,
                               const float* __restrict__ bh2,
                               const float* __restrict__ Wfuse, int nHE) {
    __shared__ float f[8][128];
    __shared__ float sred[8][4];
    __shared__ float satt[8];
    int tid = threadIdx.x;
    int n0 = blockIdx.x * 8;

    for (int idx = tid; idx < 1024; idx += 256) {
        int e = idx >> 7, d = idx & 127;
        int ne = n0 + e;
        f[e][d] = (ne < nHE) ? g_he_feat[ne * 128 + d] : 0.f;
    }
    if (tid < 32) ((float*)sred)[tid] = 0.f;
    __syncthreads();

    int h = tid >> 6, k = tid & 63;
    float acc[8];
#pragma unroll
    for (int e = 0; e < 8; e++) acc[e] = 0.f;

    const float* wp = Wh1 + h * 128 * 64 + k;
#pragma unroll 4
    for (int d = 0; d < 128; d++) {
        float w = __ldg(wp + d * 64);
#pragma unroll
        for (int e = 0; e < 8; e++) acc[e] += f[e][d] * w;
    }
    float b1 = __ldg(bh1 + h * 64 + k);
    float w2 = __ldg(Wh2 + h * 64 + k);
#pragma unroll
    for (int e = 0; e < 8; e++) {
        float v = fmaxf(acc[e] + b1, 0.f) * w2;
#pragma unroll
        for (int o = 16; o; o >>= 1) v += __shfl_xor_sync(0xffffffffu, v, o);
        if ((tid & 31) == 0) atomicAdd(&sred[e][h], v);
    }
    __syncthreads();

    if (tid < 8) {
        float a = 0.f;
#pragma unroll
        for (int hh = 0; hh < 4; hh++) {
            float s = 1.f / (1.f + expf(-(sred[tid][hh] + bh2[hh])));
            a += s * Wfuse[hh];
        }
        satt[tid] = a;
    }
    __syncthreads();

    for (int idx = tid; idx < 1024; idx += 256) {
        int e = idx >> 7, d = idx & 127;
        int ne = n0 + e;
        if (ne < nHE) g_he_weighted[ne * 128 + d] = f[e][d] * satt[e];
    }
}

// ---------------------------------------------------------------------------
// Stage 3: cluster[pid] += he_weighted[hid] * ew
// ---------------------------------------------------------------------------
__global__ void scatter_cluster_kernel(const float* __restrict__ ew,
                                       const int* __restrict__ pid,
                                       const int* __restrict__ hid, int nE) {
    int gt = blockIdx.x * blockDim.x + threadIdx.x;
    int e = gt >> 5;
    int lane = gt & 31;
    if (e >= nE) return;
    int p = __ldg(pid + e);
    int h = __ldg(hid + e);
    float w = __ldg(ew + e);
    float4 v = *(const float4*)(g_he_weighted + h * 128 + lane * 4);
    float* dst = g_cluster + p * 128 + lane * 4;
    asm volatile("red.global.add.v4.f32 [%0], {%1,%2,%3,%4};"
                 :: "l"(dst), "f"(v.x * w), "f"(v.y * w), "f"(v.z * w), "f"(v.w * w)
                 : "memory");
}

// ---------------------------------------------------------------------------
// GEMM machinery: 128x128 block tile, 256 threads, 8x8 thread tile, FFMA2.
// Thread (tx = tid&15, ty = tid>>4): rows {ty + 16*j}, cols {8*tx .. 8*tx+7}.
// Weight rows stored de-conflicted: float4 group c4 -> slot ((c4&1)<<4)|(c4>>1),
// i.e. [even groups | odd groups], so each LDS.128 phase tiles all 32 banks.
// ---------------------------------------------------------------------------
typedef unsigned long long ull;

__device__ __forceinline__ ull pack2(float x) {
    ull r;
    unsigned int xi = __float_as_uint(x);
    asm("mov.b64 %0, {%1, %1};" : "=l"(r) : "r"(xi));
    return r;
}
__device__ __forceinline__ void fma2(ull& d, ull a, ull b) {
    asm("fma.rn.f32x2 %0, %1, %2, %0;" : "+l"(d) : "l"(a), "l"(b));
}
__device__ __forceinline__ float2 unpack2(ull v) {
    unsigned int lo, hi;
    asm("mov.b64 {%0, %1}, %2;" : "=r"(lo), "=r"(hi) : "l"(v));
    float2 f;
    f.x = __uint_as_float(lo);
    f.y = __uint_as_float(hi);
    return f;
}

// load one 32x128 weight chunk into regs (4 float4 / thread)
__device__ __forceinline__ void ldw(const float* __restrict__ W, int NW, int colOff,
                                    int k0, int tid, float4 pf[4]) {
#pragma unroll
    for (int i = 0; i < 4; i++) {
        int g = tid + 256 * i;
        int r = g >> 5, c4 = g & 31;
        pf[i] = __ldg((const float4*)(W + (size_t)(k0 + r) * NW + colOff) + c4);
    }
}
// store regs -> smem with the even/odd permutation
__device__ __forceinline__ void stw(float* sWb, int tid, const float4 pf[4]) {
#pragma unroll
    for (int i = 0; i < 4; i++) {
        int g = tid + 256 * i;
        int r = g >> 5, c4 = g & 31;
        int slot = ((c4 & 1) << 4) | (c4 >> 1);
        *(float4*)(sWb + r * 128 + slot * 4) = pf[i];
    }
}
// 32-k inner product accumulate
__device__ __forceinline__ void mm32(const float* sAk, int lda, const float* sWb,
                                     int tx, int ty, ull acc[8][4]) {
#pragma unroll 8
    for (int k = 0; k < 32; k++) {
        const float* br = sWb + k * 128;
        const ull* p0 = (const ull*)(br + tx * 4);
        const ull* p1 = (const ull*)(br + 64 + tx * 4);
        ull b0 = p0[0], b1 = p0[1], b2 = p1[0], b3 = p1[1];
#pragma unroll
        for (int j = 0; j < 8; j++) {
            ull pa = pack2(sAk[(ty + 16 * j) * lda + k]);
            fma2(acc[j][0], pa, b0);
            fma2(acc[j][1], pa, b1);
            fma2(acc[j][2], pa, b2);
            fma2(acc[j][3], pa, b3);
        }
    }
}

// ---------------------------------------------------------------------------
// Kernel A: projections.  y=0: self_f = feat@Wself+bself -> g_cat[:,0:128]
//                         y=1: clu_f  = cluster@Wclu+bclu -> g_cat[:,128:256]
// ---------------------------------------------------------------------------
#define LDA_P 132
#define SMEM_A_BYTES (128 * LDA_P * 4 + 2 * 32 * 128 * 4)   // 100352

__global__ void __launch_bounds__(256, 2)
proj_kernel(const float* __restrict__ feat,
            const float* __restrict__ Wself, const float* __restrict__ bself,
            const float* __restrict__ Wclu, const float* __restrict__ bclu,
            int nP) {
    extern __shared__ float sm[];
    float* sA = sm;
    float* sW = sm + 128 * LDA_P;

    int tid = threadIdx.x;
    int tx = tid & 15, ty = tid >> 4;
    int row0 = blockIdx.x * 128;
    int y = blockIdx.y;
    const float* A = y ? g_cluster : feat;
    const float* W = y ? Wclu : Wself;
    const float* bias = y ? bclu : bself;

    // stage A tile (128x128, lda=132)
#pragma unroll
    for (int i = 0; i < 16; i++) {
        int g = tid + 256 * i;
        int r = g >> 5, c4 = g & 31;
        int grow = row0 + r;
        float4 v = {0.f, 0.f, 0.f, 0.f};
        if (grow < nP) v = __ldg((const float4*)(A + (size_t)grow * 128) + c4);
        *(float4*)(sA + r * LDA_P + c4 * 4) = v;
    }

    ull acc[8][4];
#pragma unroll
    for (int j = 0; j < 8; j++)
#pragma unroll
        for (int i = 0; i < 4; i++) acc[j][i] = 0ull;

    float4 pf[4];
    ldw(W, 128, 0, 0, tid, pf);
    stw(sW, tid, pf);
    __syncthreads();
#pragma unroll
    for (int ch = 0; ch < 4; ch++) {
        if (ch < 3) ldw(W, 128, 0, (ch + 1) * 32, tid, pf);
        mm32(sA + ch * 32, LDA_P, sW + (ch & 1) * 4096, tx, ty, acc);
        __syncthreads();
        if (ch < 3) {
            stw(sW + ((ch + 1) & 1) * 4096, tid, pf);
            __syncthreads();
        }
    }

    // epilogue -> g_cat
    float* outBase = g_cat + y * 128;
#pragma unroll
    for (int j = 0; j < 8; j++) {
        int grow = row0 + ty + 16 * j;
        if (grow >= nP) continue;
        float* orow = outBase + (size_t)grow * 256 + tx * 8;
#pragma unroll
        for (int i = 0; i < 4; i++) {
            float2 v = unpack2(acc[j][i]);
            v.x += __ldg(bias + tx * 8 + 2 * i);
            v.y += __ldg(bias + tx * 8 + 2 * i + 1);
            *(float2*)(orow + 2 * i) = v;
        }
    }
}

// ---------------------------------------------------------------------------
// Kernel B: t1 = relu(cat @ Wf1 + bf1) -> g_t1.  y selects 128-col half.
// ---------------------------------------------------------------------------
#define LDA_C 260
#define SMEM_B_BYTES (128 * LDA_C * 4 + 2 * 32 * 128 * 4)   // 165888

__global__ void __launch_bounds__(256, 1)
mlp1_kernel(const float* __restrict__ Wf1, const float* __restrict__ bf1, int nP) {
    extern __shared__ float sm[];
    float* sA = sm;
    float* sW = sm + 128 * LDA_C;

    int tid = threadIdx.x;
    int tx = tid & 15, ty = tid >> 4;
    int row0 = blockIdx.x * 128;
    int colOff = blockIdx.y * 128;

    // stage cat tile (128x256)
#pragma unroll
    for (int i = 0; i < 32; i++) {
        int g = tid + 256 * i;
        int r = g >> 6, c4 = g & 63;
        int grow = row0 + r;
        float4 v = {0.f, 0.f, 0.f, 0.f};
        if (grow < nP) v = __ldg((const float4*)(g_cat + (size_t)grow * 256) + c4);
        *(float4*)(sA + r * LDA_C + c4 * 4) = v;
    }

    ull acc[8][4];
#pragma unroll
    for (int j = 0; j < 8; j++)
#pragma unroll
        for (int i = 0; i < 4; i++) acc[j][i] = 0ull;

    float4 pf[4];
    ldw(Wf1, 256, colOff, 0, tid, pf);
    stw(sW, tid, pf);
    __syncthreads();
#pragma unroll
    for (int ch = 0; ch < 8; ch++) {
        if (ch < 7) ldw(Wf1, 256, colOff, (ch + 1) * 32, tid, pf);
        mm32(sA + ch * 32, LDA_C, sW + (ch & 1) * 4096, tx, ty, acc);
        __syncthreads();
        if (ch < 7) {
            stw(sW + ((ch + 1) & 1) * 4096, tid, pf);
            __syncthreads();
        }
    }

    float* outBase = g_t1 + colOff;
#pragma unroll
    for (int j = 0; j < 8; j++) {
        int grow = row0 + ty + 16 * j;
        if (grow >= nP) continue;
        float* orow = outBase + (size_t)grow * 256 + tx * 8;
#pragma unroll
        for (int i = 0; i < 4; i++) {
            float2 v = unpack2(acc[j][i]);
            v.x = fmaxf(v.x + __ldg(bf1 + colOff + tx * 8 + 2 * i), 0.f);
            v.y = fmaxf(v.y + __ldg(bf1 + colOff + tx * 8 + 2 * i + 1), 0.f);
            *(float2*)(orow + 2 * i) = v;
        }
    }
}

// ---------------------------------------------------------------------------
// Kernel C: t2 = relu(t1 @ Wf2 + bf2); fw = softmax(t2 @ Wf3 + bf3);
//           out = relu(self_f*fw0 + clu_f*fw1 + feat)
// ---------------------------------------------------------------------------
#define LDT2 129
// smem (floats): sA 128*260 | sW 32*128 | sT2 128*129 | sFW 256
#define C_OFF_W  (128 * LDA_C)
#define C_OFF_T2 (C_OFF_W + 32 * 128)
#define C_OFF_FW (C_OFF_T2 + 128 * LDT2)
#define SMEM_C_BYTES ((C_OFF_FW + 256) * 4)                 // 216576

__global__ void __launch_bounds__(256, 1)
mlp2_kernel(const float* __restrict__ feat,
            const float* __restrict__ Wf2, const float* __restrict__ bf2,
            const float* __restrict__ Wf3, const float* __restrict__ bf3,
            float* __restrict__ out, int nP) {
    extern __shared__ float sm[];
    float* sA = sm;
    float* sW = sm + C_OFF_W;
    float* sT2 = sm + C_OFF_T2;
    float* sFW = sm + C_OFF_FW;

    int tid = threadIdx.x;
    int tx = tid & 15, ty = tid >> 4;
    int row0 = blockIdx.x * 128;

    // stage t1 tile (128x256)
#pragma unroll
    for (int i = 0; i < 32; i++) {
        int g = tid + 256 * i;
        int r = g >> 6, c4 = g & 63;
        int grow = row0 + r;
        float4 v = {0.f, 0.f, 0.f, 0.f};
        if (grow < nP) v = __ldg((const float4*)(g_t1 + (size_t)grow * 256) + c4);
        *(float4*)(sA + r * LDA_C + c4 * 4) = v;
    }

    ull acc[8][4];
#pragma unroll
    for (int j = 0; j < 8; j++)
#pragma unroll
        for (int i = 0; i < 4; i++) acc[j][i] = 0ull;

    float4 pf[4];
#pragma unroll
    for (int ch = 0; ch < 8; ch++) {
        ldw(Wf2, 128, 0, ch * 32, tid, pf);
        if (ch == 0) __syncthreads();   // A staging visible before first compute
        stw(sW, tid, pf);
        __syncthreads();
        mm32(sA + ch * 32, LDA_C, sW, tx, ty, acc);
        __syncthreads();
    }

    // epilogue -> sT2 (relu)
#pragma unroll
    for (int j = 0; j < 8; j++) {
        float* trow = sT2 + (ty + 16 * j) * LDT2 + tx * 8;
#pragma unroll
        for (int i = 0; i < 4; i++) {
            float2 v = unpack2(acc[j][i]);
            trow[2 * i]     = fmaxf(v.x + __ldg(bf2 + tx * 8 + 2 * i), 0.f);
            trow[2 * i + 1] = fmaxf(v.y + __ldg(bf2 + tx * 8 + 2 * i + 1), 0.f);
        }
    }
    __syncthreads();

    // f3 + softmax per row
    if (tid < 128) {
        float l0 = __ldg(bf3), l1 = __ldg(bf3 + 1);
        const float* trow = sT2 + tid * LDT2;
#pragma unroll 8
        for (int k = 0; k < 128; k++) {
            float v = trow[k];
            l0 += v * __ldg(Wf3 + 2 * k);
            l1 += v * __ldg(Wf3 + 2 * k + 1);
        }
        float w0 = 1.f / (1.f + expf(l1 - l0));
        sFW[2 * tid] = w0;
        sFW[2 * tid + 1] = 1.f - w0;
    }
    __syncthreads();

    // final fuse
    for (int idx = tid; idx < 128 * 32; idx += 256) {
        int r = idx >> 5, c4 = idx & 31;
        int grow = row0 + r;
        if (grow >= nP) continue;
        float w0 = sFW[2 * r], w1 = sFW[2 * r + 1];
        float4 s  = __ldg((const float4*)(g_cat + (size_t)grow * 256) + c4);
        float4 cl = __ldg((const float4*)(g_cat + (size_t)grow * 256 + 128) + c4);
        float4 f  = __ldg((const float4*)(feat + (size_t)grow * 128) + c4);
        float4 o;
        o.x = fmaxf(s.x * w0 + cl.x * w1 + f.x, 0.f);
        o.y = fmaxf(s.y * w0 + cl.y * w1 + f.y, 0.f);
        o.z = fmaxf(s.z * w0 + cl.z * w1 + f.z, 0.f);
        o.w = fmaxf(s.w * w0 + cl.w * w1 + f.w, 0.f);
        *(float4*)(out + (size_t)grow * 128 + c4 * 4) = o;
    }
}

// ---------------------------------------------------------------------------
extern "C" void kernel_launch(void* const* d_in, const int* in_sizes, int n_in,
                              void* d_out, int out_size) {
    const float* feat   = (const float*)d_in[0];
    const float* edge_w = (const float*)d_in[1];
    const float* Wself  = (const float*)d_in[2];
    const float* bself  = (const float*)d_in[3];
    const float* Wclu   = (const float*)d_in[4];
    const float* bclu   = (const float*)d_in[5];
    const float* Wh1    = (const float*)d_in[6];
    const float* bh1    = (const float*)d_in[7];
    const float* Wh2    = (const float*)d_in[8];
    const float* bh2    = (const float*)d_in[9];
    const float* Wfuse  = (const float*)d_in[10];
    const float* Wf1    = (const float*)d_in[11];
    const float* bf1    = (const float*)d_in[12];
    const float* Wf2    = (const float*)d_in[13];
    const float* bf2    = (const float*)d_in[14];
    const float* Wf3    = (const float*)d_in[15];
    const float* bf3    = (const float*)d_in[16];
    const int* edge_pid = (const int*)d_in[17];
    const int* edge_hid = (const int*)d_in[18];

    int nP  = in_sizes[0] / 128;
    int nE  = in_sizes[17];
    int nHE = NHE_MAX;

    zero_bufs_kernel<<<(NP_MAX * DIN / 4 + 255) / 256, 256>>>();

    {
        long long threads = (long long)nE * 32;
        int blocks = (int)((threads + 255) / 256);
        scatter_he_kernel<<<blocks, 256>>>(feat, edge_w, edge_pid, edge_hid, nE);
    }

    he_attn_kernel<<<(nHE + 7) / 8, 256>>>(Wh1, bh1, Wh2, bh2, Wfuse, nHE);

    {
        long long threads = (long long)nE * 32;
        int blocks = (int)((threads + 255) / 256);
        scatter_cluster_kernel<<<blocks, 256>>>(edge_w, edge_pid, edge_hid, nE);
    }

    int nBlk = (nP + 127) / 128;

    cudaFuncSetAttribute(proj_kernel, cudaFuncAttributeMaxDynamicSharedMemorySize,
                         SMEM_A_BYTES);
    proj_kernel<<<dim3(nBlk, 2), 256, SMEM_A_BYTES>>>(feat, Wself, bself, Wclu, bclu, nP);

    cudaFuncSetAttribute(mlp1_kernel, cudaFuncAttributeMaxDynamicSharedMemorySize,
                         SMEM_B_BYTES);
    mlp1_kernel<<<dim3(nBlk, 2), 256, SMEM_B_BYTES>>>(Wf1, bf1, nP);

    cudaFuncSetAttribute(mlp2_kernel, cudaFuncAttributeMaxDynamicSharedMemorySize,
                         SMEM_C_BYTES);
    mlp2_kernel<<<nBlk, 256, SMEM_C_BYTES>>>(feat, Wf2, bf2, Wf3, bf3,
                                             (float*)d_out, nP);
}

// round 4
// speedup vs baseline: 1.8596x; 1.4760x over previous
#include <cuda_runtime.h>
#include <cuda_bf16.h>
#include <math.h>
#include <stdint.h>

#define NP_MAX 50000
#define NHE_MAX 5000
#define DIN 128

// ---------------------------------------------------------------------------
// Device scratch (no allocations allowed)
// ---------------------------------------------------------------------------
__device__ float g_he_feat[NHE_MAX * DIN];       // 2.56 MB
__device__ float g_he_weighted[NHE_MAX * DIN];   // 2.56 MB
__device__ float g_cluster[NP_MAX * DIN];        // 25.6 MB
__device__ float g_cat[NP_MAX * 256];            // 51.2 MB  [self_f | clu_f]
__device__ float g_t1[NP_MAX * 256];             // 51.2 MB

// bf16 weight images, plain [n][k] row-major (n = output col, k = input dim):
// img 0: Wself | 1: Wclu | 2,3: Wf1 colhalf0 chunk0/1 | 4,5: Wf1 colhalf1 | 6,7: Wf2
__device__ __align__(16) __nv_bfloat16 g_wimg_hi[8][128 * 128];
__device__ __align__(16) __nv_bfloat16 g_wimg_lo[8][128 * 128];

__device__ __forceinline__ unsigned int packbf2(__nv_bfloat16 a, __nv_bfloat16 b) {
    return ((unsigned int)__bfloat16_as_ushort(b) << 16) | __bfloat16_as_ushort(a);
}

// ---------------------------------------------------------------------------
// mma.sync m16n8k16 bf16 (baseline PTX, HMMA on sm_103)
// ---------------------------------------------------------------------------
__device__ __forceinline__ void mma_bf16(float* d, const unsigned* a, const unsigned* b) {
    asm volatile(
        "mma.sync.aligned.m16n8k16.row.col.f32.bf16.bf16.f32 "
        "{%0,%1,%2,%3}, {%4,%5,%6,%7}, {%8,%9}, {%0,%1,%2,%3};"
        : "+f"(d[0]), "+f"(d[1]), "+f"(d[2]), "+f"(d[3])
        : "r"(a[0]), "r"(a[1]), "r"(a[2]), "r"(a[3]), "r"(b[0]), "r"(b[1]));
}

// ---------------------------------------------------------------------------
// SMEM: A hi/lo + B hi/lo, each [128][136] bf16 (stride 272 B = 68 words:
// fragment LDS bank = (4*row + kq) mod 32 -> conflict-free).
// ---------------------------------------------------------------------------
#define LDBF 136
#define STRB 272
#define OFF_AHI 0
#define OFF_ALO (128 * STRB)
#define OFF_BHI (2 * 128 * STRB)
#define OFF_BLO (3 * 128 * STRB)
#define TC_SMEM_BYTES (4 * 128 * STRB)   // 139264

// Stage A chunk [128 rows x 128 k] fp32 -> bf16 hi/lo split into smem
__device__ __forceinline__ void stage_A(const float* __restrict__ A, int ldA,
                                        int row0, int nP, int k0,
                                        char* sAhi, char* sAlo, int tid) {
#pragma unroll
    for (int i = 0; i < 16; i++) {
        int g = tid + 256 * i;
        int r = g >> 5, c4 = g & 31;           // c4: float4 index within row
        int grow = row0 + r;
        float4 v = {0.f, 0.f, 0.f, 0.f};
        if (grow < nP)
            v = __ldg((const float4*)(A + (size_t)grow * ldA + k0) + c4);
        __nv_bfloat16 h0 = __float2bfloat16(v.x), h1 = __float2bfloat16(v.y);
        __nv_bfloat16 h2 = __float2bfloat16(v.z), h3 = __float2bfloat16(v.w);
        __nv_bfloat16 l0 = __float2bfloat16(v.x - __bfloat162float(h0));
        __nv_bfloat16 l1 = __float2bfloat16(v.y - __bfloat162float(h1));
        __nv_bfloat16 l2 = __float2bfloat16(v.z - __bfloat162float(h2));
        __nv_bfloat16 l3 = __float2bfloat16(v.w - __bfloat162float(h3));
        uint2 hu, lu;
        hu.x = packbf2(h0, h1); hu.y = packbf2(h2, h3);
        lu.x = packbf2(l0, l1); lu.y = packbf2(l2, l3);
        int off = r * STRB + c4 * 8;           // 272 % 8 == 0 -> aligned
        *(uint2*)(sAhi + off) = hu;
        *(uint2*)(sAlo + off) = lu;
    }
}

// Copy 32 KB weight image into padded smem layout
__device__ __forceinline__ void copy_B(const __nv_bfloat16* hi, const __nv_bfloat16* lo,
                                       char* sBhi, char* sBlo, int tid) {
#pragma unroll
    for (int i = 0; i < 8; i++) {
        int idx = tid + 256 * i;               // 2048 uint4
        int r = idx >> 4, kg = idx & 15;
        uint4 h = __ldg((const uint4*)hi + idx);
        uint4 l = __ldg((const uint4*)lo + idx);
        *(uint4*)(sBhi + r * STRB + kg * 16) = h;   // 272 % 16 == 0
        *(uint4*)(sBlo + r * STRB + kg * 16) = l;
    }
}

// One K=128 chunk of HMMA for this warp's 32x64 tile. acc[2][8][4].
__device__ __forceinline__ void hmma_chunk(const char* sm, int warpM, int warpN,
                                           int lane, float acc[2][8][4]) {
    int qr = lane >> 2, qc = lane & 3;
    const char* sAhi = sm + OFF_AHI;
    const char* sAlo = sm + OFF_ALO;
    const char* sBhi = sm + OFF_BHI;
    const char* sBlo = sm + OFF_BLO;
#pragma unroll
    for (int ks = 0; ks < 8; ks++) {
        int k0 = ks * 16;
        unsigned ah[2][4], al[2][4];
#pragma unroll
        for (int mt = 0; mt < 2; mt++) {
            int r = warpM + mt * 16 + qr;
            int cb = (k0 + qc * 2) * 2;        // byte offset of k element
            const char* p0 = sAhi + r * STRB + cb;
            const char* p1 = sAhi + (r + 8) * STRB + cb;
            ah[mt][0] = *(const unsigned*)p0;
            ah[mt][1] = *(const unsigned*)p1;
            ah[mt][2] = *(const unsigned*)(p0 + 16);
            ah[mt][3] = *(const unsigned*)(p1 + 16);
            const char* q0 = sAlo + r * STRB + cb;
            const char* q1 = sAlo + (r + 8) * STRB + cb;
            al[mt][0] = *(const unsigned*)q0;
            al[mt][1] = *(const unsigned*)q1;
            al[mt][2] = *(const unsigned*)(q0 + 16);
            al[mt][3] = *(const unsigned*)(q1 + 16);
        }
#pragma unroll
        for (int nt = 0; nt < 8; nt++) {
            int n = warpN + nt * 8 + qr;
            int cb = (k0 + qc * 2) * 2;
            unsigned bh[2], bl[2];
            const char* pb = sBhi + n * STRB + cb;
            bh[0] = *(const unsigned*)pb;
            bh[1] = *(const unsigned*)(pb + 16);
            const char* pl = sBlo + n * STRB + cb;
            bl[0] = *(const unsigned*)pl;
            bl[1] = *(const unsigned*)(pl + 16);
#pragma unroll
            for (int mt = 0; mt < 2; mt++) {
                mma_bf16(acc[mt][nt], ah[mt], bh);
                mma_bf16(acc[mt][nt], ah[mt], bl);
                mma_bf16(acc[mt][nt], al[mt], bh);
            }
        }
    }
}

// Epilogue: acc -> global fp32 with bias (+opt relu)
__device__ __forceinline__ void epi_global(const float acc[2][8][4],
                                           const float* __restrict__ bias,
                                           float* __restrict__ outBase, int ldOut,
                                           int row0, int nP, bool relu,
                                           int warpM, int warpN, int lane) {
    int qr = lane >> 2, qc = lane & 3;
#pragma unroll
    for (int mt = 0; mt < 2; mt++) {
#pragma unroll
        for (int nt = 0; nt < 8; nt++) {
            int col = warpN + nt * 8 + qc * 2;
            float b0 = __ldg(bias + col), b1 = __ldg(bias + col + 1);
            int r0 = row0 + warpM + mt * 16 + qr;
#pragma unroll
            for (int half = 0; half < 2; half++) {
                int grow = r0 + half * 8;
                if (grow < nP) {
                    float2 v;
                    v.x = acc[mt][nt][half * 2 + 0] + b0;
                    v.y = acc[mt][nt][half * 2 + 1] + b1;
                    if (relu) { v.x = fmaxf(v.x, 0.f); v.y = fmaxf(v.y, 0.f); }
                    *(float2*)(outBase + (size_t)grow * ldOut + col) = v;
                }
            }
        }
    }
}

// ---------------------------------------------------------------------------
__global__ void zero_bufs_kernel() {
    int i = blockIdx.x * blockDim.x + threadIdx.x;
    float4 z = {0.f, 0.f, 0.f, 0.f};
    if (i < (NHE_MAX * DIN) / 4) ((float4*)g_he_feat)[i] = z;
    if (i < (NP_MAX * DIN) / 4)  ((float4*)g_cluster)[i] = z;
}

// Weight prep: transpose + bf16 hi/lo split into [n][k] images
__global__ void prep_weights(const float* __restrict__ Wself,
                             const float* __restrict__ Wclu,
                             const float* __restrict__ Wf1,
                             const float* __restrict__ Wf2) {
    int g = blockIdx.x * 256 + threadIdx.x;   // 131072 total
    int img = g >> 14;
    int e = g & 16383;
    int n = e >> 7, k = e & 127;
    float val;
    switch (img) {
        case 0: val = __ldg(Wself + k * 128 + n); break;
        case 1: val = __ldg(Wclu + k * 128 + n); break;
        case 2: val = __ldg(Wf1 + k * 256 + n); break;
        case 3: val = __ldg(Wf1 + (128 + k) * 256 + n); break;
        case 4: val = __ldg(Wf1 + k * 256 + 128 + n); break;
        case 5: val = __ldg(Wf1 + (128 + k) * 256 + 128 + n); break;
        case 6: val = __ldg(Wf2 + k * 128 + n); break;
        default: val = __ldg(Wf2 + (128 + k) * 128 + n); break;
    }
    __nv_bfloat16 hi = __float2bfloat16(val);
    __nv_bfloat16 lo = __float2bfloat16(val - __bfloat162float(hi));
    g_wimg_hi[img][e] = hi;
    g_wimg_lo[img][e] = lo;
}

// ---------------------------------------------------------------------------
// Stage 1: he_feat[hid] += feat[pid] * ew
// ---------------------------------------------------------------------------
__global__ void scatter_he_kernel(const float* __restrict__ feat,
                                  const float* __restrict__ ew,
                                  const int* __restrict__ pid,
                                  const int* __restrict__ hid, int nE) {
    int gt = blockIdx.x * blockDim.x + threadIdx.x;
    int e = gt >> 5;
    int lane = gt & 31;
    if (e >= nE) return;
    int p = __ldg(pid + e);
    int h = __ldg(hid + e);
    float w = __ldg(ew + e);
    float4 v = __ldg(((const float4*)feat) + p * 32 + lane);
    float* dst = g_he_feat + h * 128 + lane * 4;
    asm volatile("red.global.add.v4.f32 [%0], {%1,%2,%3,%4};"
                 :: "l"(dst), "f"(v.x * w), "f"(v.y * w), "f"(v.z * w), "f"(v.w * w)
                 : "memory");
}

// ---------------------------------------------------------------------------
// Stage 2: per-hyperedge attention -> he_weighted
// ---------------------------------------------------------------------------
__global__ void he_attn_kernel(const float* __restrict__ Wh1,
                               const float* __restrict__ bh1,
                               const float* __restrict__ Wh2,
                               const float* __restrict__ bh2,
                               const float* __restrict__ Wfuse, int nHE) {
    __shared__ float f[8][128];
    __shared__ float sred[8][4];
    __shared__ float satt[8];
    int tid = threadIdx.x;
    int n0 = blockIdx.x * 8;

    for (int idx = tid; idx < 1024; idx += 256) {
        int e = idx >> 7, d = idx & 127;
        int ne = n0 + e;
        f[e][d] = (ne < nHE) ? g_he_feat[ne * 128 + d] : 0.f;
    }
    if (tid < 32) ((float*)sred)[tid] = 0.f;
    __syncthreads();

    int h = tid >> 6, k = tid & 63;
    float acc[8];
#pragma unroll
    for (int e = 0; e < 8; e++) acc[e] = 0.f;

    const float* wp = Wh1 + h * 128 * 64 + k;
#pragma unroll 4
    for (int d = 0; d < 128; d++) {
        float w = __ldg(wp + d * 64);
#pragma unroll
        for (int e = 0; e < 8; e++) acc[e] += f[e][d] * w;
    }
    float b1 = __ldg(bh1 + h * 64 + k);
    float w2 = __ldg(Wh2 + h * 64 + k);
#pragma unroll
    for (int e = 0; e < 8; e++) {
        float v = fmaxf(acc[e] + b1, 0.f) * w2;
#pragma unroll
        for (int o = 16; o; o >>= 1) v += __shfl_xor_sync(0xffffffffu, v, o);
        if ((tid & 31) == 0) atomicAdd(&sred[e][h], v);
    }
    __syncthreads();

    if (tid < 8) {
        float a = 0.f;
#pragma unroll
        for (int hh = 0; hh < 4; hh++) {
            float s = 1.f / (1.f + expf(-(sred[tid][hh] + bh2[hh])));
            a += s * Wfuse[hh];
        }
        satt[tid] = a;
    }
    __syncthreads();

    for (int idx = tid; idx < 1024; idx += 256) {
        int e = idx >> 7, d = idx & 127;
        int ne = n0 + e;
        if (ne < nHE) g_he_weighted[ne * 128 + d] = f[e][d] * satt[e];
    }
}

// ---------------------------------------------------------------------------
// Stage 3: cluster[pid] += he_weighted[hid] * ew
// ---------------------------------------------------------------------------
__global__ void scatter_cluster_kernel(const float* __restrict__ ew,
                                       const int* __restrict__ pid,
                                       const int* __restrict__ hid, int nE) {
    int gt = blockIdx.x * blockDim.x + threadIdx.x;
    int e = gt >> 5;
    int lane = gt & 31;
    if (e >= nE) return;
    int p = __ldg(pid + e);
    int h = __ldg(hid + e);
    float w = __ldg(ew + e);
    float4 v = *(const float4*)(g_he_weighted + h * 128 + lane * 4);
    float* dst = g_cluster + p * 128 + lane * 4;
    asm volatile("red.global.add.v4.f32 [%0], {%1,%2,%3,%4};"
                 :: "l"(dst), "f"(v.x * w), "f"(v.y * w), "f"(v.z * w), "f"(v.w * w)
                 : "memory");
}

// ---------------------------------------------------------------------------
// GEMM A: projections.  y=0: feat@Wself+bself -> g_cat[:,0:128]
//                       y=1: g_cluster@Wclu+bclu -> g_cat[:,128:256]
// ---------------------------------------------------------------------------
__global__ void __launch_bounds__(256, 1)
proj_tc(const float* __restrict__ feat,
        const float* __restrict__ bself, const float* __restrict__ bclu, int nP) {
    extern __shared__ char smem[];
    int tid = threadIdx.x;
    int wid = tid >> 5, lane = tid & 31;
    int warpM = (wid & 3) * 32, warpN = (wid >> 2) * 64;
    int y = blockIdx.y;
    int row0 = blockIdx.x * 128;
    const float* A = y ? g_cluster : feat;
    const float* bias = y ? bclu : bself;

    float acc[2][8][4];
#pragma unroll
    for (int m = 0; m < 2; m++)
#pragma unroll
        for (int n = 0; n < 8; n++)
#pragma unroll
            for (int i = 0; i < 4; i++) acc[m][n][i] = 0.f;

    stage_A(A, 128, row0, nP, 0, smem + OFF_AHI, smem + OFF_ALO, tid);
    copy_B(g_wimg_hi[y], g_wimg_lo[y], smem + OFF_BHI, smem + OFF_BLO, tid);
    __syncthreads();
    hmma_chunk(smem, warpM, warpN, lane, acc);

    epi_global(acc, bias, g_cat + y * 128, 256, row0, nP, false, warpM, warpN, lane);
}

// ---------------------------------------------------------------------------
// GEMM B: t1 = relu(g_cat @ Wf1 + bf1), K=256 (2 chunks). y = column half.
// ---------------------------------------------------------------------------
__global__ void __launch_bounds__(256, 1)
mlp1_tc(const float* __restrict__ bf1, int nP) {
    extern __shared__ char smem[];
    int tid = threadIdx.x;
    int wid = tid >> 5, lane = tid & 31;
    int warpM = (wid & 3) * 32, warpN = (wid >> 2) * 64;
    int y = blockIdx.y;
    int row0 = blockIdx.x * 128;
    int colOff = y * 128;

    float acc[2][8][4];
#pragma unroll
    for (int m = 0; m < 2; m++)
#pragma unroll
        for (int n = 0; n < 8; n++)
#pragma unroll
            for (int i = 0; i < 4; i++) acc[m][n][i] = 0.f;

#pragma unroll
    for (int ch = 0; ch < 2; ch++) {
        if (ch) __syncthreads();
        stage_A(g_cat, 256, row0, nP, ch * 128, smem + OFF_AHI, smem + OFF_ALO, tid);
        copy_B(g_wimg_hi[2 + y * 2 + ch], g_wimg_lo[2 + y * 2 + ch],
               smem + OFF_BHI, smem + OFF_BLO, tid);
        __syncthreads();
        hmma_chunk(smem, warpM, warpN, lane, acc);
    }

    epi_global(acc, bf1 + colOff, g_t1 + colOff, 256, row0, nP, true,
               warpM, warpN, lane);
}

// ---------------------------------------------------------------------------
// GEMM C: t2 = relu(g_t1 @ Wf2 + bf2); fw = softmax(t2@Wf3+bf3);
//         out = relu(self_f*fw0 + clu_f*fw1 + feat)
// ---------------------------------------------------------------------------
#define LDT2 129
__global__ void __launch_bounds__(256, 1)
mlp2_tc(const float* __restrict__ feat,
        const float* __restrict__ bf2,
        const float* __restrict__ Wf3, const float* __restrict__ bf3,
        float* __restrict__ out, int nP) {
    extern __shared__ char smem[];
    int tid = threadIdx.x;
    int wid = tid >> 5, lane = tid & 31;
    int warpM = (wid & 3) * 32, warpN = (wid >> 2) * 64;
    int row0 = blockIdx.x * 128;

    float acc[2][8][4];
#pragma unroll
    for (int m = 0; m < 2; m++)
#pragma unroll
        for (int n = 0; n < 8; n++)
#pragma unroll
            for (int i = 0; i < 4; i++) acc[m][n][i] = 0.f;

#pragma unroll
    for (int ch = 0; ch < 2; ch++) {
        if (ch) __syncthreads();
        stage_A(g_t1, 256, row0, nP, ch * 128, smem + OFF_AHI, smem + OFF_ALO, tid);
        copy_B(g_wimg_hi[6 + ch], g_wimg_lo[6 + ch],
               smem + OFF_BHI, smem + OFF_BLO, tid);
        __syncthreads();
        hmma_chunk(smem, warpM, warpN, lane, acc);
    }
    __syncthreads();   // done with A/B smem; overlay t2

    float* sT2 = (float*)smem;                     // 128*129*4 = 66048 B
    float* sFW = (float*)(smem + 128 * LDT2 * 4);  // 1024 B
    {
        int qr = lane >> 2, qc = lane & 3;
#pragma unroll
        for (int mt = 0; mt < 2; mt++) {
#pragma unroll
            for (int nt = 0; nt < 8; nt++) {
                int col = warpN + nt * 8 + qc * 2;
                float b0 = __ldg(bf2 + col), b1 = __ldg(bf2 + col + 1);
#pragma unroll
                for (int half = 0; half < 2; half++) {
                    int r = warpM + mt * 16 + qr + half * 8;
                    sT2[r * LDT2 + col] =
                        fmaxf(acc[mt][nt][half * 2 + 0] + b0, 0.f);
                    sT2[r * LDT2 + col + 1] =
                        fmaxf(acc[mt][nt][half * 2 + 1] + b1, 0.f);
                }
            }
        }
    }
    __syncthreads();

    // f3 + softmax per row
    if (tid < 128) {
        float l0 = __ldg(bf3), l1 = __ldg(bf3 + 1);
        const float* trow = sT2 + tid * LDT2;
#pragma unroll 8
        for (int k = 0; k < 128; k++) {
            float v = trow[k];
            l0 += v * __ldg(Wf3 + 2 * k);
            l1 += v * __ldg(Wf3 + 2 * k + 1);
        }
        float w0 = 1.f / (1.f + expf(l1 - l0));
        sFW[2 * tid] = w0;
        sFW[2 * tid + 1] = 1.f - w0;
    }
    __syncthreads();

    // final fuse
    for (int idx = tid; idx < 128 * 32; idx += 256) {
        int r = idx >> 5, c4 = idx & 31;
        int grow = row0 + r;
        if (grow < nP) {
            float w0 = sFW[2 * r], w1 = sFW[2 * r + 1];
            float4 s  = __ldg((const float4*)(g_cat + (size_t)grow * 256) + c4);
            float4 cl = __ldg((const float4*)(g_cat + (size_t)grow * 256 + 128) + c4);
            float4 f  = __ldg((const float4*)(feat + (size_t)grow * 128) + c4);
            float4 o;
            o.x = fmaxf(s.x * w0 + cl.x * w1 + f.x, 0.f);
            o.y = fmaxf(s.y * w0 + cl.y * w1 + f.y, 0.f);
            o.z = fmaxf(s.z * w0 + cl.z * w1 + f.z, 0.f);
            o.w = fmaxf(s.w * w0 + cl.w * w1 + f.w, 0.f);
            *(float4*)(out + (size_t)grow * 128 + c4 * 4) = o;
        }
    }
}

// ---------------------------------------------------------------------------
extern "C" void kernel_launch(void* const* d_in, const int* in_sizes, int n_in,
                              void* d_out, int out_size) {
    const float* feat   = (const float*)d_in[0];
    const float* edge_w = (const float*)d_in[1];
    const float* Wself  = (const float*)d_in[2];
    const float* bself  = (const float*)d_in[3];
    const float* Wclu   = (const float*)d_in[4];
    const float* bclu   = (const float*)d_in[5];
    const float* Wh1    = (const float*)d_in[6];
    const float* bh1    = (const float*)d_in[7];
    const float* Wh2    = (const float*)d_in[8];
    const float* bh2    = (const float*)d_in[9];
    const float* Wfuse  = (const float*)d_in[10];
    const float* Wf1    = (const float*)d_in[11];
    const float* bf1    = (const float*)d_in[12];
    const float* Wf2    = (const float*)d_in[13];
    const float* bf2    = (const float*)d_in[14];
    const float* Wf3    = (const float*)d_in[15];
    const float* bf3    = (const float*)d_in[16];
    const int* edge_pid = (const int*)d_in[17];
    const int* edge_hid = (const int*)d_in[18];

    int nP  = in_sizes[0] / 128;
    int nE  = in_sizes[17];
    int nHE = NHE_MAX;

    zero_bufs_kernel<<<(NP_MAX * DIN / 4 + 255) / 256, 256>>>();
    prep_weights<<<512, 256>>>(Wself, Wclu, Wf1, Wf2);

    {
        long long threads = (long long)nE * 32;
        int blocks = (int)((threads + 255) / 256);
        scatter_he_kernel<<<blocks, 256>>>(feat, edge_w, edge_pid, edge_hid, nE);
    }

    he_attn_kernel<<<(nHE + 7) / 8, 256>>>(Wh1, bh1, Wh2, bh2, Wfuse, nHE);

    {
        long long threads = (long long)nE * 32;
        int blocks = (int)((threads + 255) / 256);
        scatter_cluster_kernel<<<blocks, 256>>>(edge_w, edge_pid, edge_hid, nE);
    }

    int nBlk = (nP + 127) / 128;

    cudaFuncSetAttribute(proj_tc, cudaFuncAttributeMaxDynamicSharedMemorySize,
                         TC_SMEM_BYTES);
    proj_tc<<<dim3(nBlk, 2), 256, TC_SMEM_BYTES>>>(feat, bself, bclu, nP);

    cudaFuncSetAttribute(mlp1_tc, cudaFuncAttributeMaxDynamicSharedMemorySize,
                         TC_SMEM_BYTES);
    mlp1_tc<<<dim3(nBlk, 2), 256, TC_SMEM_BYTES>>>(bf1, nP);

    cudaFuncSetAttribute(mlp2_tc, cudaFuncAttributeMaxDynamicSharedMemorySize,
                         TC_SMEM_BYTES);
    mlp2_tc<<<nBlk, 256, TC_SMEM_BYTES>>>(feat, bf2, Wf3, bf3, (float*)d_out, nP);
}

// round 6
// speedup vs baseline: 2.1395x; 1.1505x over previous
#include <cuda_runtime.h>
#include <cuda_bf16.h>
#include <math.h>
#include <stdint.h>

#define NP_MAX 50000
#define NHE_MAX 5000
#define DIN 128
#define CAPH 256
#define CAPP 64

// ---------------------------------------------------------------------------
// Device scratch (no allocations allowed)
// ---------------------------------------------------------------------------
__device__ float g_he_feat[NHE_MAX * DIN];       // 2.56 MB
__device__ float g_he_weighted[NHE_MAX * DIN];   // 2.56 MB
__device__ float g_cluster[NP_MAX * DIN];        // 25.6 MB
__device__ float g_cat[NP_MAX * 256];            // 51.2 MB
__device__ float g_t1[NP_MAX * 256];             // 51.2 MB
__device__ float g_h[NHE_MAX * 256];             // 5.12 MB (attn hidden)

// Bucketed edge lists (gather form of the two segment-sums)
__device__ int2 g_bktH[NHE_MAX * CAPH];          // {pid, w}  10.2 MB
__device__ int2 g_bktP[NP_MAX * CAPP];           // {hid, w}  25.6 MB
__device__ int g_cntH[NHE_MAX];
__device__ int g_cntP[NP_MAX];
__device__ int g_ovfH_cnt, g_ovfP_cnt;
__device__ int g_ovfH[800000];
__device__ int g_ovfP[800000];

// bf16 weight images, [n][k] row-major:
// 0: Wself | 1: Wclu | 2,3: Wf1 col0 ch0/1 | 4,5: Wf1 col1 ch0/1 | 6,7: Wf2 | 8,9: Wh1
__device__ __align__(16) __nv_bfloat16 g_wimg_hi[10][128 * 128];
__device__ __align__(16) __nv_bfloat16 g_wimg_lo[10][128 * 128];

__device__ __forceinline__ unsigned int packbf2(__nv_bfloat16 a, __nv_bfloat16 b) {
    return ((unsigned int)__bfloat16_as_ushort(b) << 16) | __bfloat16_as_ushort(a);
}

// ---------------------------------------------------------------------------
// mma.sync m16n8k16 bf16 (baseline PTX, HMMA on sm_103)
// ---------------------------------------------------------------------------
__device__ __forceinline__ void mma_bf16(float* d, const unsigned* a, const unsigned* b) {
    asm volatile(
        "mma.sync.aligned.m16n8k16.row.col.f32.bf16.bf16.f32 "
        "{%0,%1,%2,%3}, {%4,%5,%6,%7}, {%8,%9}, {%0,%1,%2,%3};"
        : "+f"(d[0]), "+f"(d[1]), "+f"(d[2]), "+f"(d[3])
        : "r"(a[0]), "r"(a[1]), "r"(a[2]), "r"(a[3]), "r"(b[0]), "r"(b[1]));
}

// SMEM: A hi/lo + B hi/lo, each [128][136] bf16 (stride 272 B, conflict-free)
#define STRB 272
#define OFF_AHI 0
#define OFF_ALO (128 * STRB)
#define OFF_BHI (2 * 128 * STRB)
#define OFF_BLO (3 * 128 * STRB)
#define TC_SMEM_BYTES (4 * 128 * STRB)   // 139264

__device__ __forceinline__ void stage_A(const float* __restrict__ A, int ldA,
                                        int row0, int nP, int k0,
                                        char* sAhi, char* sAlo, int tid) {
#pragma unroll
    for (int i = 0; i < 16; i++) {
        int g = tid + 256 * i;
        int r = g >> 5, c4 = g & 31;
        int grow = row0 + r;
        float4 v = {0.f, 0.f, 0.f, 0.f};
        if (grow < nP)
            v = __ldg((const float4*)(A + (size_t)grow * ldA + k0) + c4);
        __nv_bfloat16 h0 = __float2bfloat16(v.x), h1 = __float2bfloat16(v.y);
        __nv_bfloat16 h2 = __float2bfloat16(v.z), h3 = __float2bfloat16(v.w);
        __nv_bfloat16 l0 = __float2bfloat16(v.x - __bfloat162float(h0));
        __nv_bfloat16 l1 = __float2bfloat16(v.y - __bfloat162float(h1));
        __nv_bfloat16 l2 = __float2bfloat16(v.z - __bfloat162float(h2));
        __nv_bfloat16 l3 = __float2bfloat16(v.w - __bfloat162float(h3));
        uint2 hu, lu;
        hu.x = packbf2(h0, h1); hu.y = packbf2(h2, h3);
        lu.x = packbf2(l0, l1); lu.y = packbf2(l2, l3);
        int off = r * STRB + c4 * 8;
        *(uint2*)(sAhi + off) = hu;
        *(uint2*)(sAlo + off) = lu;
    }
}

__device__ __forceinline__ void copy_B(const __nv_bfloat16* hi, const __nv_bfloat16* lo,
                                       char* sBhi, char* sBlo, int tid) {
#pragma unroll
    for (int i = 0; i < 8; i++) {
        int idx = tid + 256 * i;
        int r = idx >> 4, kg = idx & 15;
        uint4 h = __ldg((const uint4*)hi + idx);
        uint4 l = __ldg((const uint4*)lo + idx);
        *(uint4*)(sBhi + r * STRB + kg * 16) = h;
        *(uint4*)(sBlo + r * STRB + kg * 16) = l;
    }
}

__device__ __forceinline__ void hmma_chunk(const char* sm, int warpM, int warpN,
                                           int lane, float acc[2][8][4]) {
    int qr = lane >> 2, qc = lane & 3;
    const char* sAhi = sm + OFF_AHI;
    const char* sAlo = sm + OFF_ALO;
    const char* sBhi = sm + OFF_BHI;
    const char* sBlo = sm + OFF_BLO;
#pragma unroll
    for (int ks = 0; ks < 8; ks++) {
        int k0 = ks * 16;
        unsigned ah[2][4], al[2][4];
#pragma unroll
        for (int mt = 0; mt < 2; mt++) {
            int r = warpM + mt * 16 + qr;
            int cb = (k0 + qc * 2) * 2;
            const char* p0 = sAhi + r * STRB + cb;
            const char* p1 = sAhi + (r + 8) * STRB + cb;
            ah[mt][0] = *(const unsigned*)p0;
            ah[mt][1] = *(const unsigned*)p1;
            ah[mt][2] = *(const unsigned*)(p0 + 16);
            ah[mt][3] = *(const unsigned*)(p1 + 16);
            const char* q0 = sAlo + r * STRB + cb;
            const char* q1 = sAlo + (r + 8) * STRB + cb;
            al[mt][0] = *(const unsigned*)q0;
            al[mt][1] = *(const unsigned*)q1;
            al[mt][2] = *(const unsigned*)(q0 + 16);
            al[mt][3] = *(const unsigned*)(q1 + 16);
        }
#pragma unroll
        for (int nt = 0; nt < 8; nt++) {
            int n = warpN + nt * 8 + qr;
            int cb = (k0 + qc * 2) * 2;
            unsigned bh[2], bl[2];
            const char* pb = sBhi + n * STRB + cb;
            bh[0] = *(const unsigned*)pb;
            bh[1] = *(const unsigned*)(pb + 16);
            const char* pl = sBlo + n * STRB + cb;
            bl[0] = *(const unsigned*)pl;
            bl[1] = *(const unsigned*)(pl + 16);
#pragma unroll
            for (int mt = 0; mt < 2; mt++) {
                mma_bf16(acc[mt][nt], ah[mt], bh);
                mma_bf16(acc[mt][nt], ah[mt], bl);
                mma_bf16(acc[mt][nt], al[mt], bh);
            }
        }
    }
}

__device__ __forceinline__ void epi_global(const float acc[2][8][4],
                                           const float* __restrict__ bias,
                                           float* __restrict__ outBase, int ldOut,
                                           int row0, int nP, bool relu,
                                           int warpM, int warpN, int lane) {
    int qr = lane >> 2, qc = lane & 3;
#pragma unroll
    for (int mt = 0; mt < 2; mt++) {
#pragma unroll
        for (int nt = 0; nt < 8; nt++) {
            int col = warpN + nt * 8 + qc * 2;
            float b0 = __ldg(bias + col), b1 = __ldg(bias + col + 1);
            int r0 = row0 + warpM + mt * 16 + qr;
#pragma unroll
            for (int half = 0; half < 2; half++) {
                int grow = r0 + half * 8;
                if (grow < nP) {
                    float2 v;
                    v.x = acc[mt][nt][half * 2 + 0] + b0;
                    v.y = acc[mt][nt][half * 2 + 1] + b1;
                    if (relu) { v.x = fmaxf(v.x, 0.f); v.y = fmaxf(v.y, 0.f); }
                    *(float2*)(outBase + (size_t)grow * ldOut + col) = v;
                }
            }
        }
    }
}

// ---------------------------------------------------------------------------
// Setup kernels
// ---------------------------------------------------------------------------
__global__ void zero_counts_kernel() {
    int i = blockIdx.x * blockDim.x + threadIdx.x;
    if (i < NP_MAX) g_cntP[i] = 0;
    if (i < NHE_MAX) g_cntH[i] = 0;
    if (i == 0) { g_ovfH_cnt = 0; g_ovfP_cnt = 0; }
}

// Weight prep: transpose + bf16 hi/lo split into [n][k] images (10 imgs)
__global__ void prep_weights(const float* __restrict__ Wself,
                             const float* __restrict__ Wclu,
                             const float* __restrict__ Wf1,
                             const float* __restrict__ Wf2,
                             const float* __restrict__ Wh1) {
    int g = blockIdx.x * 256 + threadIdx.x;   // 163840 total
    int img = g >> 14;
    int e = g & 16383;
    int n = e >> 7, k = e & 127;
    float val;
    switch (img) {
        case 0: val = __ldg(Wself + k * 128 + n); break;
        case 1: val = __ldg(Wclu + k * 128 + n); break;
        case 2: val = __ldg(Wf1 + k * 256 + n); break;
        case 3: val = __ldg(Wf1 + (128 + k) * 256 + n); break;
        case 4: val = __ldg(Wf1 + k * 256 + 128 + n); break;
        case 5: val = __ldg(Wf1 + (128 + k) * 256 + 128 + n); break;
        case 6: val = __ldg(Wf2 + k * 128 + n); break;
        case 7: val = __ldg(Wf2 + (128 + k) * 128 + n); break;
        case 8: val = __ldg(Wh1 + ((n >> 6) * 128 + k) * 64 + (n & 63)); break;
        default: val = __ldg(Wh1 + ((2 + (n >> 6)) * 128 + k) * 64 + (n & 63)); break;
    }
    __nv_bfloat16 hi = __float2bfloat16(val);
    __nv_bfloat16 lo = __float2bfloat16(val - __bfloat162float(hi));
    g_wimg_hi[img][e] = hi;
    g_wimg_lo[img][e] = lo;
}

// ---------------------------------------------------------------------------
// Bucket fill: bin every edge by hyperedge and by protein
// ---------------------------------------------------------------------------
__global__ void bucket_fill(const int* __restrict__ pid, const int* __restrict__ hid,
                            const float* __restrict__ ew, int nE) {
    int e = blockIdx.x * 256 + threadIdx.x;
    if (e >= nE) return;
    int p = __ldg(pid + e);
    int h = __ldg(hid + e);
    float w = __ldg(ew + e);
    int s = atomicAdd(&g_cntH[h], 1);
    if (s < CAPH) g_bktH[h * CAPH + s] = make_int2(p, __float_as_int(w));
    else { int o = atomicAdd(&g_ovfH_cnt, 1); g_ovfH[o] = e; }
    s = atomicAdd(&g_cntP[p], 1);
    if (s < CAPP) g_bktP[p * CAPP + s] = make_int2(h, __float_as_int(w));
    else { int o = atomicAdd(&g_ovfP_cnt, 1); g_ovfP[o] = e; }
}

// ---------------------------------------------------------------------------
// Gather 1: he_feat[b] = sum over bucket of feat[pid] * w
// ---------------------------------------------------------------------------
__global__ void __launch_bounds__(128)
gather_he(const float* __restrict__ feat) {
    int b = blockIdx.x, d = threadIdx.x;
    int n = g_cntH[b];
    if (n > CAPH) n = CAPH;
    const int2* bk = g_bktH + b * CAPH;
    float acc = 0.f;
    int i = 0;
    for (; i + 4 <= n; i += 4) {
        int2 e0 = __ldg(bk + i), e1 = __ldg(bk + i + 1);
        int2 e2 = __ldg(bk + i + 2), e3 = __ldg(bk + i + 3);
        float f0 = __ldg(feat + (size_t)e0.x * 128 + d);
        float f1 = __ldg(feat + (size_t)e1.x * 128 + d);
        float f2 = __ldg(feat + (size_t)e2.x * 128 + d);
        float f3 = __ldg(feat + (size_t)e3.x * 128 + d);
        acc += f0 * __int_as_float(e0.y) + f1 * __int_as_float(e1.y)
             + f2 * __int_as_float(e2.y) + f3 * __int_as_float(e3.y);
    }
    for (; i < n; i++) {
        int2 e0 = __ldg(bk + i);
        acc += __ldg(feat + (size_t)e0.x * 128 + d) * __int_as_float(e0.y);
    }
    g_he_feat[b * 128 + d] = acc;
}

// Overflow replay (normally empty): he_feat[hid] += feat[pid]*w via red
__global__ void ovf_replay_he(const float* __restrict__ feat,
                              const float* __restrict__ ew,
                              const int* __restrict__ pid,
                              const int* __restrict__ hid) {
    int total = g_ovfH_cnt * 32;
    for (int t = blockIdx.x * blockDim.x + threadIdx.x; t < total;
         t += gridDim.x * blockDim.x) {
        int i = t >> 5, lane = t & 31;
        int e = g_ovfH[i];
        int p = __ldg(pid + e), h = __ldg(hid + e);
        float w = __ldg(ew + e);
        float4 v = __ldg((const float4*)feat + p * 32 + lane);
        float* dst = g_he_feat + h * 128 + lane * 4;
        asm volatile("red.global.add.v4.f32 [%0], {%1,%2,%3,%4};"
                     :: "l"(dst), "f"(v.x * w), "f"(v.y * w), "f"(v.z * w), "f"(v.w * w)
                     : "memory");
    }
}

// ---------------------------------------------------------------------------
// Attention GEMM: g_h = relu(he_feat @ Wh1 + bh1)  (imgs 8,9; y = col half)
// ---------------------------------------------------------------------------
__global__ void __launch_bounds__(256, 1)
attn_gemm(const float* __restrict__ bh1, int nHE) {
    extern __shared__ char smem[];
    int tid = threadIdx.x;
    int wid = tid >> 5, lane = tid & 31;
    int warpM = (wid & 3) * 32, warpN = (wid >> 2) * 64;
    int y = blockIdx.y;
    int row0 = blockIdx.x * 128;

    float acc[2][8][4];
#pragma unroll
    for (int m = 0; m < 2; m++)
#pragma unroll
        for (int n = 0; n < 8; n++)
#pragma unroll
            for (int i = 0; i < 4; i++) acc[m][n][i] = 0.f;

    stage_A(g_he_feat, 128, row0, nHE, 0, smem + OFF_AHI, smem + OFF_ALO, tid);
    copy_B(g_wimg_hi[8 + y], g_wimg_lo[8 + y], smem + OFF_BHI, smem + OFF_BLO, tid);
    __syncthreads();
    hmma_chunk(smem, warpM, warpN, lane, acc);

    epi_global(acc, bh1 + y * 128, g_h + y * 128, 256, row0, nHE, true,
               warpM, warpN, lane);
}

// Attention fuse: att[he] = sum_head sigmoid(dot(h, Wh2) + bh2) * Wfuse;
// he_weighted = he_feat * att.  One warp per hyperedge.
__global__ void __launch_bounds__(256)
attn_fuse(const float* __restrict__ Wh2, const float* __restrict__ bh2,
          const float* __restrict__ Wfuse, int nHE) {
    int wq = threadIdx.x >> 5, lane = threadIdx.x & 31;
    int he = blockIdx.x * 8 + wq;
    if (he >= nHE) return;
    const float* hr = g_h + (size_t)he * 256;
    float att = 0.f;
#pragma unroll
    for (int hh = 0; hh < 4; hh++) {
        float s = __ldg(hr + hh * 64 + lane) * __ldg(Wh2 + hh * 64 + lane)
                + __ldg(hr + hh * 64 + 32 + lane) * __ldg(Wh2 + hh * 64 + 32 + lane);
#pragma unroll
        for (int o = 16; o; o >>= 1) s += __shfl_xor_sync(0xffffffffu, s, o);
        float sg = 1.f / (1.f + expf(-(s + __ldg(bh2 + hh))));
        att += sg * __ldg(Wfuse + hh);
    }
    float4 f = __ldg((const float4*)(g_he_feat + (size_t)he * 128) + lane);
    f.x *= att; f.y *= att; f.z *= att; f.w *= att;
    *((float4*)(g_he_weighted + (size_t)he * 128) + lane) = f;
}

// ---------------------------------------------------------------------------
// Gather 2: cluster[p] = sum over bucket of he_weighted[hid] * w
// ---------------------------------------------------------------------------
__global__ void __launch_bounds__(128)
gather_p() {
    int p = blockIdx.x, d = threadIdx.x;
    int n = g_cntP[p];
    if (n > CAPP) n = CAPP;
    const int2* bk = g_bktP + p * CAPP;
    float acc = 0.f;
    int i = 0;
    for (; i + 4 <= n; i += 4) {
        int2 e0 = __ldg(bk + i), e1 = __ldg(bk + i + 1);
        int2 e2 = __ldg(bk + i + 2), e3 = __ldg(bk + i + 3);
        float f0 = g_he_weighted[(size_t)e0.x * 128 + d];
        float f1 = g_he_weighted[(size_t)e1.x * 128 + d];
        float f2 = g_he_weighted[(size_t)e2.x * 128 + d];
        float f3 = g_he_weighted[(size_t)e3.x * 128 + d];
        acc += f0 * __int_as_float(e0.y) + f1 * __int_as_float(e1.y)
             + f2 * __int_as_float(e2.y) + f3 * __int_as_float(e3.y);
    }
    for (; i < n; i++) {
        int2 e0 = __ldg(bk + i);
        acc += g_he_weighted[(size_t)e0.x * 128 + d] * __int_as_float(e0.y);
    }
    g_cluster[p * 128 + d] = acc;
}

__global__ void ovf_replay_p(const float* __restrict__ ew,
                             const int* __restrict__ pid,
                             const int* __restrict__ hid) {
    int total = g_ovfP_cnt * 32;
    for (int t = blockIdx.x * blockDim.x + threadIdx.x; t < total;
         t += gridDim.x * blockDim.x) {
        int i = t >> 5, lane = t & 31;
        int e = g_ovfP[i];
        int p = __ldg(pid + e), h = __ldg(hid + e);
        float w = __ldg(ew + e);
        float4 v = *(const float4*)(g_he_weighted + h * 128 + lane * 4);
        float* dst = g_cluster + p * 128 + lane * 4;
        asm volatile("red.global.add.v4.f32 [%0], {%1,%2,%3,%4};"
                     :: "l"(dst), "f"(v.x * w), "f"(v.y * w), "f"(v.z * w), "f"(v.w * w)
                     : "memory");
    }
}

// ---------------------------------------------------------------------------
// GEMM A: projections (y=0 feat@Wself, y=1 cluster@Wclu) -> g_cat halves
// ---------------------------------------------------------------------------
__global__ void __launch_bounds__(256, 1)
proj_tc(const float* __restrict__ feat,
        const float* __restrict__ bself, const float* __restrict__ bclu, int nP) {
    extern __shared__ char smem[];
    int tid = threadIdx.x;
    int wid = tid >> 5, lane = tid & 31;
    int warpM = (wid & 3) * 32, warpN = (wid >> 2) * 64;
    int y = blockIdx.y;
    int row0 = blockIdx.x * 128;
    const float* A = y ? g_cluster : feat;
    const float* bias = y ? bclu : bself;

    float acc[2][8][4];
#pragma unroll
    for (int m = 0; m < 2; m++)
#pragma unroll
        for (int n = 0; n < 8; n++)
#pragma unroll
            for (int i = 0; i < 4; i++) acc[m][n][i] = 0.f;

    stage_A(A, 128, row0, nP, 0, smem + OFF_AHI, smem + OFF_ALO, tid);
    copy_B(g_wimg_hi[y], g_wimg_lo[y], smem + OFF_BHI, smem + OFF_BLO, tid);
    __syncthreads();
    hmma_chunk(smem, warpM, warpN, lane, acc);

    epi_global(acc, bias, g_cat + y * 128, 256, row0, nP, false, warpM, warpN, lane);
}

// ---------------------------------------------------------------------------
// GEMM B: t1 = relu(g_cat @ Wf1 + bf1), K=256 (2 chunks). y = column half.
// ---------------------------------------------------------------------------
__global__ void __launch_bounds__(256, 1)
mlp1_tc(const float* __restrict__ bf1, int nP) {
    extern __shared__ char smem[];
    int tid = threadIdx.x;
    int wid = tid >> 5, lane = tid & 31;
    int warpM = (wid & 3) * 32, warpN = (wid >> 2) * 64;
    int y = blockIdx.y;
    int row0 = blockIdx.x * 128;
    int colOff = y * 128;

    float acc[2][8][4];
#pragma unroll
    for (int m = 0; m < 2; m++)
#pragma unroll
        for (int n = 0; n < 8; n++)
#pragma unroll
            for (int i = 0; i < 4; i++) acc[m][n][i] = 0.f;

#pragma unroll
    for (int ch = 0; ch < 2; ch++) {
        if (ch) __syncthreads();
        stage_A(g_cat, 256, row0, nP, ch * 128, smem + OFF_AHI, smem + OFF_ALO, tid);
        copy_B(g_wimg_hi[2 + y * 2 + ch], g_wimg_lo[2 + y * 2 + ch],
               smem + OFF_BHI, smem + OFF_BLO, tid);
        __syncthreads();
        hmma_chunk(smem, warpM, warpN, lane, acc);
    }

    epi_global(acc, bf1 + colOff, g_t1 + colOff, 256, row0, nP, true,
               warpM, warpN, lane);
}

// ---------------------------------------------------------------------------
// GEMM C: t2 = relu(g_t1 @ Wf2 + bf2); fw = softmax(t2@Wf3+bf3);
//         out = relu(self_f*fw0 + clu_f*fw1 + feat)
// ---------------------------------------------------------------------------
#define LDT2 129
__global__ void __launch_bounds__(256, 1)
mlp2_tc(const float* __restrict__ feat,
        const float* __restrict__ bf2,
        const float* __restrict__ Wf3, const float* __restrict__ bf3,
        float* __restrict__ out, int nP) {
    extern __shared__ char smem[];
    int tid = threadIdx.x;
    int wid = tid >> 5, lane = tid & 31;
    int warpM = (wid & 3) * 32, warpN = (wid >> 2) * 64;
    int row0 = blockIdx.x * 128;

    float acc[2][8][4];
#pragma unroll
    for (int m = 0; m < 2; m++)
#pragma unroll
        for (int n = 0; n < 8; n++)
#pragma unroll
            for (int i = 0; i < 4; i++) acc[m][n][i] = 0.f;

#pragma unroll
    for (int ch = 0; ch < 2; ch++) {
        if (ch) __syncthreads();
        stage_A(g_t1, 256, row0, nP, ch * 128, smem + OFF_AHI, smem + OFF_ALO, tid);
        copy_B(g_wimg_hi[6 + ch], g_wimg_lo[6 + ch],
               smem + OFF_BHI, smem + OFF_BLO, tid);
        __syncthreads();
        hmma_chunk(smem, warpM, warpN, lane, acc);
    }
    __syncthreads();

    float* sT2 = (float*)smem;
    float* sFW = (float*)(smem + 128 * LDT2 * 4);
    {
        int qr = lane >> 2, qc = lane & 3;
#pragma unroll
        for (int mt = 0; mt < 2; mt++) {
#pragma unroll
            for (int nt = 0; nt < 8; nt++) {
                int col = warpN + nt * 8 + qc * 2;
                float b0 = __ldg(bf2 + col), b1 = __ldg(bf2 + col + 1);
#pragma unroll
                for (int half = 0; half < 2; half++) {
                    int r = warpM + mt * 16 + qr + half * 8;
                    sT2[r * LDT2 + col] =
                        fmaxf(acc[mt][nt][half * 2 + 0] + b0, 0.f);
                    sT2[r * LDT2 + col + 1] =
                        fmaxf(acc[mt][nt][half * 2 + 1] + b1, 0.f);
                }
            }
        }
    }
    __syncthreads();

    if (tid < 128) {
        float l0 = __ldg(bf3), l1 = __ldg(bf3 + 1);
        const float* trow = sT2 + tid * LDT2;
#pragma unroll 8
        for (int k = 0; k < 128; k++) {
            float v = trow[k];
            l0 += v * __ldg(Wf3 + 2 * k);
            l1 += v * __ldg(Wf3 + 2 * k + 1);
        }
        float w0 = 1.f / (1.f + expf(l1 - l0));
        sFW[2 * tid] = w0;
        sFW[2 * tid + 1] = 1.f - w0;
    }
    __syncthreads();

    for (int idx = tid; idx < 128 * 32; idx += 256) {
        int r = idx >> 5, c4 = idx & 31;
        int grow = row0 + r;
        if (grow < nP) {
            float w0 = sFW[2 * r], w1 = sFW[2 * r + 1];
            float4 s  = __ldg((const float4*)(g_cat + (size_t)grow * 256) + c4);
            float4 cl = __ldg((const float4*)(g_cat + (size_t)grow * 256 + 128) + c4);
            float4 f  = __ldg((const float4*)(feat + (size_t)grow * 128) + c4);
            float4 o;
            o.x = fmaxf(s.x * w0 + cl.x * w1 + f.x, 0.f);
            o.y = fmaxf(s.y * w0 + cl.y * w1 + f.y, 0.f);
            o.z = fmaxf(s.z * w0 + cl.z * w1 + f.z, 0.f);
            o.w = fmaxf(s.w * w0 + cl.w * w1 + f.w, 0.f);
            *(float4*)(out + (size_t)grow * 128 + c4 * 4) = o;
        }
    }
}

// ---------------------------------------------------------------------------
extern "C" void kernel_launch(void* const* d_in, const int* in_sizes, int n_in,
                              void* d_out, int out_size) {
    const float* feat   = (const float*)d_in[0];
    const float* edge_w = (const float*)d_in[1];
    const float* Wself  = (const float*)d_in[2];
    const float* bself  = (const float*)d_in[3];
    const float* Wclu   = (const float*)d_in[4];
    const float* bclu   = (const float*)d_in[5];
    const float* Wh1    = (const float*)d_in[6];
    const float* bh1    = (const float*)d_in[7];
    const float* Wh2    = (const float*)d_in[8];
    const float* bh2    = (const float*)d_in[9];
    const float* Wfuse  = (const float*)d_in[10];
    const float* Wf1    = (const float*)d_in[11];
    const float* bf1    = (const float*)d_in[12];
    const float* Wf2    = (const float*)d_in[13];
    const float* bf2    = (const float*)d_in[14];
    const float* Wf3    = (const float*)d_in[15];
    const float* bf3    = (const float*)d_in[16];
    const int* edge_pid = (const int*)d_in[17];
    const int* edge_hid = (const int*)d_in[18];

    int nP  = in_sizes[0] / 128;
    int nE  = in_sizes[17];
    int nHE = NHE_MAX;

    zero_counts_kernel<<<(NP_MAX + 255) / 256, 256>>>();
    prep_weights<<<640, 256>>>(Wself, Wclu, Wf1, Wf2, Wh1);
    bucket_fill<<<(nE + 255) / 256, 256>>>(edge_pid, edge_hid, edge_w, nE);

    gather_he<<<nHE, 128>>>(feat);
    ovf_replay_he<<<64, 256>>>(feat, edge_w, edge_pid, edge_hid);

    int nBlkH = (nHE + 127) / 128;
    cudaFuncSetAttribute(attn_gemm, cudaFuncAttributeMaxDynamicSharedMemorySize,
                         TC_SMEM_BYTES);
    attn_gemm<<<dim3(nBlkH, 2), 256, TC_SMEM_BYTES>>>(bh1, nHE);
    attn_fuse<<<(nHE + 7) / 8, 256>>>(Wh2, bh2, Wfuse, nHE);

    gather_p<<<nP, 128>>>();
    ovf_replay_p<<<64, 256>>>(edge_w, edge_pid, edge_hid);

    int nBlk = (nP + 127) / 128;
    cudaFuncSetAttribute(proj_tc, cudaFuncAttributeMaxDynamicSharedMemorySize,
                         TC_SMEM_BYTES);
    proj_tc<<<dim3(nBlk, 2), 256, TC_SMEM_BYTES>>>(feat, bself, bclu, nP);

    cudaFuncSetAttribute(mlp1_tc, cudaFuncAttributeMaxDynamicSharedMemorySize,
                         TC_SMEM_BYTES);
    mlp1_tc<<<dim3(nBlk, 2), 256, TC_SMEM_BYTES>>>(bf1, nP);

    cudaFuncSetAttribute(mlp2_tc, cudaFuncAttributeMaxDynamicSharedMemorySize,
                         TC_SMEM_BYTES);
    mlp2_tc<<<nBlk, 256, TC_SMEM_BYTES>>>(feat, bf2, Wf3, bf3, (float*)d_out, nP);
}